// round 8
// baseline (speedup 1.0000x reference)
#include <cuda_runtime.h>
#include <math.h>

// ---- problem config ----
#define BB 4
#define NN 16384
#define REG_CH 76
#define POST 128
#define PSEL 512               // candidate budget (>> expected 128th-kept rank)
#define CANDP 1024             // primary sort size
#define CANDF 4096             // fallback sort size
#define NMS_THRESH 0.8f
#define TWO_PI_F 6.2831853071795864769f
#define PI_F 3.14159265358979323846f
#define APC_F 0.52359877559829887308f       // 2pi/12
#define APC_HALF_F 0.26179938779914943654f  // pi/12
#define NEG_INF_F (-__int_as_float(0x7f800000))

// ---- dynamic smem layout (bytes); regions time-multiplexed ----
// phase 1: keys [0,65536) | hist [65536,81920) | cand [81920,114688)
// phase 2: sup [0,32768) | bev4 [32768,40960) | sar [40960,43008)
//          box [43008,57344) | score [57344,59392) | cand alive until decode done
#define OFF_KEYS   0
#define OFF_SUP    0                       // 512*16 u32 = 32768
#define OFF_BEV4   32768                   // 512 float4 = 8192
#define OFF_SAR    (OFF_BEV4 + PSEL * 16)  // 512 f32 = 2048
#define OFF_BOX    (OFF_SAR + PSEL * 4)    // 512*7 f32 = 14336
#define OFF_SCORE  (OFF_BOX + PSEL * 28)   // 512 f32 -> ends 59392
#define OFF_HIST   65536                   // 4096 u32 = 16384
#define OFF_CAND   81920                   // 4096 u64 = 32768
#define SMEM_BYTES 114688

__device__ __forceinline__ unsigned desc_key(float f) {
    unsigned u = __float_as_uint(f);
    unsigned asc = (u & 0x80000000u) ? ~u : (u | 0x80000000u);
    return ~asc;   // ascending key order == descending score order
}
__device__ __forceinline__ float key_to_score(unsigned desc) {
    unsigned asc = ~desc;
    unsigned u = (asc & 0x80000000u) ? (asc ^ 0x80000000u) : ~asc;
    return __uint_as_float(u);
}

// hybrid bitonic sort, n in {1024, 4096}, 1024 threads.
__device__ __forceinline__ void bitonic_hybrid(unsigned long long* a, int n, int tid) {
    const int lane = tid & 31;
    const int wid = tid >> 5;
    for (int k = 2; k <= n; k <<= 1) {
        for (int j = k >> 1; j >= 32; j >>= 1) {
            for (int i = tid; i < n; i += 1024) {
                int ixj = i ^ j;
                if (ixj > i) {
                    unsigned long long x = a[i], y = a[ixj];
                    bool asc = ((i & k) == 0);
                    if ((x > y) == asc) { a[i] = y; a[ixj] = x; }
                }
            }
            __syncthreads();
        }
        int jtop = (k >> 1) < 16 ? (k >> 1) : 16;
        for (int g = wid; g < (n >> 5); g += 32) {
            int i = (g << 5) + lane;
            unsigned long long v = a[i];
            bool asc = ((i & k) == 0);
            for (int j = jtop; j >= 1; j >>= 1) {
                unsigned long long p = __shfl_xor_sync(0xffffffffu, v, j);
                bool takemin = (((lane & j) == 0) == asc);
                v = takemin ? (v < p ? v : p) : (v > p ? v : p);
            }
            a[i] = v;
        }
        __syncthreads();
    }
}

// warp argmax over 12 lanes starting at active_lo; cv = value or -inf.
// returns bin index (first max, matching jnp.argmax; inputs have no NaN)
__device__ __forceinline__ int warp_argmax(float cv, int active_lo) {
    float m = cv;
    #pragma unroll
    for (int d = 16; d; d >>= 1) m = fmaxf(m, __shfl_xor_sync(0xffffffffu, m, d));
    unsigned b = __ballot_sync(0xffffffffu, cv == m);
    return (__ffs(b) - 1) - active_lo;
}

// broadcast element at absolute position pos (0..95) from lane-strided regs
__device__ __forceinline__ float warp_select(float v0, float v1, float v2, int pos) {
    float a = __shfl_sync(0xffffffffu, v0, pos & 31);
    float b = __shfl_sync(0xffffffffu, v1, pos & 31);
    float c = __shfl_sync(0xffffffffu, v2, pos & 31);
    return pos < 32 ? a : (pos < 64 ? b : c);
}

// ============================================================
// One block per image: select+sort top-512 -> warp-per-row decode ->
// balanced mask -> warp-serial greedy -> gather.
// ============================================================
__global__ void __launch_bounds__(1024, 1)
fused_kernel(const float* __restrict__ scores,
             const float* __restrict__ reg,
             const float* __restrict__ xyz,
             const float* __restrict__ anchor,
             float* __restrict__ out) {
    extern __shared__ char sm[];
    uint4*    skeys4 = (uint4*)(sm + OFF_KEYS);
    unsigned* hist = (unsigned*)(sm + OFF_HIST);
    unsigned long long* cand = (unsigned long long*)(sm + OFF_CAND);
    unsigned* sup = (unsigned*)(sm + OFF_SUP);
    float4* sbev = (float4*)(sm + OFF_BEV4);     // (x1,z1,x2,z2)
    float* sar = (float*)(sm + OFF_SAR);
    float* boxS = (float*)(sm + OFF_BOX);
    float* scoreS = (float*)(sm + OFF_SCORE);

    __shared__ unsigned wsum[32];
    __shared__ int sT, sCnt, sKeepCnt;
    __shared__ int keep[POST];

    const int img = blockIdx.x;
    const int tid = threadIdx.x;
    const int lane = tid & 31;
    const int wid = tid >> 5;
    const float4* sc4 = (const float4*)(scores + (size_t)img * NN);

    // ========== Stage A: single-pass keys + histogram ==========
    for (int b = tid; b < 4096; b += 1024) hist[b] = 0;
    if (tid == 0) { sT = 4096; sCnt = 0; }
    __syncthreads();

    #pragma unroll
    for (int c = 0; c < 4; c++) {
        float4 v = sc4[c * 1024 + tid];
        unsigned k0 = desc_key(v.x), k1 = desc_key(v.y);
        unsigned k2 = desc_key(v.z), k3 = desc_key(v.w);
        skeys4[c * 1024 + tid] = make_uint4(k0, k1, k2, k3);
        atomicAdd(&hist[k0 >> 20], 1u);
        atomicAdd(&hist[k1 >> 20], 1u);
        atomicAdd(&hist[k2 >> 20], 1u);
        atomicAdd(&hist[k3 >> 20], 1u);
    }
    __syncthreads();

    // blocked inclusive prefix scan of hist[4096]
    {
        int b0 = tid * 4;
        unsigned v0 = hist[b0], v1 = hist[b0 + 1], v2 = hist[b0 + 2], v3 = hist[b0 + 3];
        unsigned i1 = v0 + v1, i2 = i1 + v2, i3 = i2 + v3;
        unsigned x = i3;
        #pragma unroll
        for (int d = 1; d < 32; d <<= 1) {
            unsigned y = __shfl_up_sync(0xffffffffu, x, d);
            if (lane >= d) x += y;
        }
        if (lane == 31) wsum[wid] = x;
        __syncthreads();
        if (wid == 0) {
            unsigned w = wsum[lane];
            #pragma unroll
            for (int d = 1; d < 32; d <<= 1) {
                unsigned y = __shfl_up_sync(0xffffffffu, w, d);
                if (lane >= d) w += y;
            }
            wsum[lane] = w;
        }
        __syncthreads();
        unsigned excl = ((wid > 0) ? wsum[wid - 1] : 0u) + (x - i3);
        hist[b0]     = excl + v0;
        hist[b0 + 1] = excl + i1;
        hist[b0 + 2] = excl + i2;
        hist[b0 + 3] = excl + i3;
        __syncthreads();
        #pragma unroll
        for (int k = 0; k < 4; k++)
            if (hist[b0 + k] >= PSEL) atomicMin(&sT, b0 + k);
    }
    __syncthreads();
    const unsigned T = (unsigned)sT;
    const int C = (int)hist[T];
    __syncthreads();

    // ========== compact candidates from smem keys ==========
    const int NS = (C <= CANDP) ? CANDP : CANDF;
    #pragma unroll
    for (int c = 0; c < 4; c++) {
        uint4 kv = skeys4[c * 1024 + tid];
        int base = (c * 1024 + tid) * 4;
        if ((kv.x >> 20) <= T) {
            int pos = atomicAdd(&sCnt, 1);
            if (pos < CANDF) cand[pos] = ((unsigned long long)kv.x << 32) | (unsigned)(base + 0);
        }
        if ((kv.y >> 20) <= T) {
            int pos = atomicAdd(&sCnt, 1);
            if (pos < CANDF) cand[pos] = ((unsigned long long)kv.y << 32) | (unsigned)(base + 1);
        }
        if ((kv.z >> 20) <= T) {
            int pos = atomicAdd(&sCnt, 1);
            if (pos < CANDF) cand[pos] = ((unsigned long long)kv.z << 32) | (unsigned)(base + 2);
        }
        if ((kv.w >> 20) <= T) {
            int pos = atomicAdd(&sCnt, 1);
            if (pos < CANDF) cand[pos] = ((unsigned long long)kv.w << 32) | (unsigned)(base + 3);
        }
    }
    __syncthreads();
    for (int p = C + tid; p < NS; p += 1024)
        cand[p] = 0xffffffffffffffffull;
    __syncthreads();

    bitonic_hybrid(cand, NS, tid);
    // keys dead from here; region reused by sup/bev/box/score

    // ========== Stage B: decode top-512 (warp-per-row, coalesced) ==========
    const float ah = anchor[0], aw = anchor[1], al = anchor[2];
    for (int row = wid; row < PSEL; row += 32) {
        unsigned long long key = cand[row];          // uniform -> broadcast LDS
        int idx = (int)(key & 0xffffffffu);
        const float* r = reg + (size_t)(img * NN + idx) * REG_CH;
        const float* p = xyz + (size_t)(img * NN + idx) * 3;

        // coalesced row load: 3 x 128B (last partial, guarded)
        float v0 = r[lane];
        float v1 = r[32 + lane];
        float v2 = (lane < REG_CH - 64) ? r[64 + lane] : 0.0f;

        int xb = warp_argmax(lane < 12 ? v0 : NEG_INF_F, 0);
        int zb = warp_argmax((lane >= 12 && lane < 24) ? v0 : NEG_INF_F, 12);
        int rb = warp_argmax((lane >= 17 && lane < 29) ? v1 : NEG_INF_F, 17); // pos 49..60

        float resx = warp_select(v0, v1, v2, 24 + xb);
        float resz = warp_select(v0, v1, v2, 36 + zb);
        float resr = warp_select(v0, v1, v2, 61 + rb);
        float yoff = __shfl_sync(0xffffffffu, v1, 16);   // pos 48
        float hin  = __shfl_sync(0xffffffffu, v2, 9);    // pos 73
        float win  = __shfl_sync(0xffffffffu, v2, 10);   // pos 74
        float lin  = __shfl_sync(0xffffffffu, v2, 11);   // pos 75

        float px = p[0], py = p[1], pz = p[2];           // uniform-addr loads

        float pos_x = __fadd_rn(__fsub_rn(__fadd_rn(__fmul_rn((float)xb, 0.5f), 0.25f), 3.0f),
                                __fmul_rn(resx, 0.5f));
        float pos_z = __fadd_rn(__fsub_rn(__fadd_rn(__fmul_rn((float)zb, 0.5f), 0.25f), 3.0f),
                                __fmul_rn(resz, 0.5f));
        float x = __fadd_rn(pos_x, px);
        float z = __fadd_rn(pos_z, pz);
        float y = __fadd_rn(py, yoff);

        float ry = __fadd_rn(__fmul_rn((float)rb, APC_F), __fmul_rn(resr, APC_HALF_F));
        float rem = fmodf(ry, TWO_PI_F);
        if (rem != 0.0f && rem < 0.0f) rem = __fadd_rn(rem, TWO_PI_F);
        ry = rem;
        if (ry > PI_F) ry = __fsub_rn(ry, TWO_PI_F);

        float h = __fadd_rn(__fmul_rn(hin, ah), ah);
        float w = __fadd_rn(__fmul_rn(win, aw), aw);
        float l = __fadd_rn(__fmul_rn(lin, al), al);
        y = __fadd_rn(y, __fmul_rn(h, 0.5f));

        float bo = (lane == 0) ? x : (lane == 1) ? y : (lane == 2) ? z :
                   (lane == 3) ? h : (lane == 4) ? w : (lane == 5) ? l : ry;
        if (lane < 7) boxS[row * 7 + lane] = bo;

        float x1 = __fsub_rn(x, __fmul_rn(l, 0.5f));
        float x2 = __fadd_rn(x, __fmul_rn(l, 0.5f));
        float z1 = __fsub_rn(z, __fmul_rn(w, 0.5f));
        float z2 = __fadd_rn(z, __fmul_rn(w, 0.5f));
        if (lane == 0) {
            sbev[row] = make_float4(x1, z1, x2, z2);
            sar[row] = __fmul_rn(__fsub_rn(x2, x1), __fsub_rn(z2, z1));
            scoreS[row] = key_to_score((unsigned)(key >> 32));
        }
    }
    __syncthreads();

    // ========== Stage C: balanced pairwise suppression bitmask ==========
    // thread handles complementary rows (i, 511-i) -> uniform ~128 IoUs/thread
    {
        const int ia = tid & 255;                // 0..255
        const int wset = (tid >> 8) & 3;         // 0..3
        #pragma unroll
        for (int half = 0; half < 2; half++) {
            const int i = half ? (PSEL - 1 - ia) : ia;
            float4 bi = sbev[i];
            float ai = sar[i];
            #pragma unroll
            for (int p = 0; p < 4; p++) {
                int w = wset + 4 * p;
                unsigned bits = 0;
                int jbase = w << 5;
                if (jbase + 31 > i) {
                    #pragma unroll 4
                    for (int b = 0; b < 32; b++) {
                        int j = jbase + b;
                        if (j <= i) continue;
                        float4 bj = sbev[j];
                        float iw = fmaxf(__fsub_rn(fminf(bi.z, bj.z), fmaxf(bi.x, bj.x)), 0.0f);
                        float ih = fmaxf(__fsub_rn(fminf(bi.w, bj.w), fmaxf(bi.y, bj.y)), 0.0f);
                        float inter = __fmul_rn(iw, ih);
                        if (inter > 0.0f) {
                            float denom = __fsub_rn(__fadd_rn(ai, sar[j]), inter);
                            float iou = __fdiv_rn(inter, denom);
                            if (iou > NMS_THRESH) bits |= (1u << b);
                        }
                    }
                }
                sup[i * 16 + w] = bits;
            }
        }
    }
    __syncthreads();

    // ========== Stage D: warp-serial greedy (warp 0, no barriers) ==========
    if (wid == 0) {
        unsigned alive = (lane < 16) ? 0xffffffffu : 0u;   // 512-bit alive set
        int cnt = 0;
        while (cnt < POST) {
            unsigned first = alive ? (unsigned)((lane << 5) + __ffs(alive) - 1)
                                   : 0xffffffffu;
            unsigned i = __reduce_min_sync(0xffffffffu, first);
            if (i == 0xffffffffu) break;
            if (lane == 0) keep[cnt] = (int)i;
            cnt++;
            if (cnt == POST) break;
            unsigned srow = (lane < 16) ? sup[i * 16 + lane] : 0u;
            alive &= ~srow;
            if (lane == (int)(i >> 5)) alive &= ~(1u << (i & 31));
        }
        if (lane == 0) sKeepCnt = cnt;
    }
    __syncthreads();

    // ========== Stage E: gather output ==========
    const int cnt = sKeepCnt;
    float* ob = out + (size_t)img * POST * 7;
    float* os = out + (size_t)BB * POST * 7 + (size_t)img * POST;
    if (tid < POST) {
        int p = tid;
        if (p < cnt) {
            int ki = keep[p];
            const float* bo = boxS + ki * 7;
            #pragma unroll
            for (int c = 0; c < 7; c++) ob[p * 7 + c] = bo[c];
            os[p] = scoreS[ki];
        } else {
            #pragma unroll
            for (int c = 0; c < 7; c++) ob[p * 7 + c] = 0.0f;
            os[p] = 0.0f;
        }
    }
}

// ============================================================
extern "C" void kernel_launch(void* const* d_in, const int* in_sizes, int n_in,
                              void* d_out, int out_size) {
    const float* scores = (const float*)d_in[0];   // (B,N)
    const float* reg    = (const float*)d_in[1];   // (B,N,76)
    const float* xyz    = (const float*)d_in[2];   // (B,N,3)
    const float* anchor = (const float*)d_in[3];   // (3,)
    float* out = (float*)d_out;

    static bool attr_set = false;
    if (!attr_set) {
        cudaFuncSetAttribute(fused_kernel,
                             cudaFuncAttributeMaxDynamicSharedMemorySize,
                             SMEM_BYTES);
        attr_set = true;
    }

    fused_kernel<<<BB, 1024, SMEM_BYTES>>>(scores, reg, xyz, anchor, out);
}

// round 9
// speedup vs baseline: 1.4270x; 1.4270x over previous
#include <cuda_runtime.h>
#include <math.h>

// ---- problem config ----
#define BB 4
#define NN 16384
#define REG_CH 76
#define POST 128
#define PSEL 512               // candidate budget (>> expected 128th-kept rank)
#define CANDP 1024             // primary sort size
#define CANDF 4096             // fallback sort size
#define NMS_THRESH 0.8f
#define TWO_PI_F 6.2831853071795864769f
#define PI_F 3.14159265358979323846f
#define APC_F 0.52359877559829887308f       // 2pi/12
#define APC_HALF_F 0.26179938779914943654f  // pi/12

#define RSTRIDE 79             // 76 reg + 3 xyz; odd -> conflict-free LDS

// ---- dynamic smem layout (bytes); regions time-multiplexed ----
// phase 1 (hist/compact/sort): keys [0,65536) | hist [65536,81920) | cand [161792,194560)
// phase 2 (copy/decode):       rowsbuf [0,161792) | cand | score/bev/sar/box high
// phase 3 (mask/greedy):       sup [0,32768) | bev/sar/box/score high
#define OFF_ROWS   0                        // 512*79*4 = 161792
#define OFF_KEYS   0                        // 16384 u32 keys = 65536
#define OFF_HIST   65536                    // 4096 u32 = 16384
#define OFF_CAND   161792                   // 4096 u64 = 32768 -> 194560
#define OFF_SCORE  194560                   // 512 f32 = 2048  -> 196608
#define OFF_BEV4   196608                   // 512 float4 = 8192 -> 204800
#define OFF_SAR    204800                   // 512 f32 = 2048  -> 206848
#define OFF_BOX    206848                   // 512*7 f32 = 14336 -> 221184
#define OFF_SUP    0                        // 512*16 u32 = 32768 (phase 3)
#define SMEM_BYTES 221184

__device__ __forceinline__ unsigned desc_key(float f) {
    unsigned u = __float_as_uint(f);
    unsigned asc = (u & 0x80000000u) ? ~u : (u | 0x80000000u);
    return ~asc;   // ascending key order == descending score order
}
__device__ __forceinline__ float key_to_score(unsigned desc) {
    unsigned asc = ~desc;
    unsigned u = (asc & 0x80000000u) ? (asc ^ 0x80000000u) : ~asc;
    return __uint_as_float(u);
}

// hybrid bitonic sort, n in {1024, 4096}, 1024 threads.
__device__ __forceinline__ void bitonic_hybrid(unsigned long long* a, int n, int tid) {
    const int lane = tid & 31;
    const int wid = tid >> 5;
    for (int k = 2; k <= n; k <<= 1) {
        for (int j = k >> 1; j >= 32; j >>= 1) {
            for (int i = tid; i < n; i += 1024) {
                int ixj = i ^ j;
                if (ixj > i) {
                    unsigned long long x = a[i], y = a[ixj];
                    bool asc = ((i & k) == 0);
                    if ((x > y) == asc) { a[i] = y; a[ixj] = x; }
                }
            }
            __syncthreads();
        }
        int jtop = (k >> 1) < 16 ? (k >> 1) : 16;
        for (int g = wid; g < (n >> 5); g += 32) {
            int i = (g << 5) + lane;
            unsigned long long v = a[i];
            bool asc = ((i & k) == 0);
            for (int j = jtop; j >= 1; j >>= 1) {
                unsigned long long p = __shfl_xor_sync(0xffffffffu, v, j);
                bool takemin = (((lane & j) == 0) == asc);
                v = takemin ? (v < p ? v : p) : (v > p ? v : p);
            }
            a[i] = v;
        }
        __syncthreads();
    }
}

// ============================================================
// One block per image.
// ============================================================
__global__ void __launch_bounds__(1024, 1)
fused_kernel(const float* __restrict__ scores,
             const float* __restrict__ reg,
             const float* __restrict__ xyz,
             const float* __restrict__ anchor,
             float* __restrict__ out) {
    extern __shared__ char sm[];
    uint4*    skeys4 = (uint4*)(sm + OFF_KEYS);
    unsigned* hist = (unsigned*)(sm + OFF_HIST);
    unsigned long long* cand = (unsigned long long*)(sm + OFF_CAND);
    float* rowsbuf = (float*)(sm + OFF_ROWS);
    unsigned* sup = (unsigned*)(sm + OFF_SUP);
    float4* sbev = (float4*)(sm + OFF_BEV4);     // (x1,z1,x2,z2)
    float* sar = (float*)(sm + OFF_SAR);
    float* boxS = (float*)(sm + OFF_BOX);
    float* scoreS = (float*)(sm + OFF_SCORE);

    __shared__ unsigned wsum[32];
    __shared__ unsigned zrow[16];     // per-box "suppresses anything" bitmap
    __shared__ int sT, sCnt, sKeepCnt;
    __shared__ int keep[POST];

    const int img = blockIdx.x;
    const int tid = threadIdx.x;
    const int lane = tid & 31;
    const int wid = tid >> 5;
    const float4* sc4 = (const float4*)(scores + (size_t)img * NN);

    // ========== Stage A: single-pass keys + histogram ==========
    for (int b = tid; b < 4096; b += 1024) hist[b] = 0;
    if (tid == 0) { sT = 4096; sCnt = 0; }
    if (tid < 16) zrow[tid] = 0;
    __syncthreads();

    #pragma unroll
    for (int c = 0; c < 4; c++) {
        float4 v = sc4[c * 1024 + tid];
        unsigned k0 = desc_key(v.x), k1 = desc_key(v.y);
        unsigned k2 = desc_key(v.z), k3 = desc_key(v.w);
        skeys4[c * 1024 + tid] = make_uint4(k0, k1, k2, k3);
        atomicAdd(&hist[k0 >> 20], 1u);
        atomicAdd(&hist[k1 >> 20], 1u);
        atomicAdd(&hist[k2 >> 20], 1u);
        atomicAdd(&hist[k3 >> 20], 1u);
    }
    __syncthreads();

    // blocked inclusive prefix scan of hist[4096]
    {
        int b0 = tid * 4;
        unsigned v0 = hist[b0], v1 = hist[b0 + 1], v2 = hist[b0 + 2], v3 = hist[b0 + 3];
        unsigned i1 = v0 + v1, i2 = i1 + v2, i3 = i2 + v3;
        unsigned x = i3;
        #pragma unroll
        for (int d = 1; d < 32; d <<= 1) {
            unsigned y = __shfl_up_sync(0xffffffffu, x, d);
            if (lane >= d) x += y;
        }
        if (lane == 31) wsum[wid] = x;
        __syncthreads();
        if (wid == 0) {
            unsigned w = wsum[lane];
            #pragma unroll
            for (int d = 1; d < 32; d <<= 1) {
                unsigned y = __shfl_up_sync(0xffffffffu, w, d);
                if (lane >= d) w += y;
            }
            wsum[lane] = w;
        }
        __syncthreads();
        unsigned excl = ((wid > 0) ? wsum[wid - 1] : 0u) + (x - i3);
        hist[b0]     = excl + v0;
        hist[b0 + 1] = excl + i1;
        hist[b0 + 2] = excl + i2;
        hist[b0 + 3] = excl + i3;
        __syncthreads();
        #pragma unroll
        for (int k = 0; k < 4; k++)
            if (hist[b0 + k] >= PSEL) atomicMin(&sT, b0 + k);
    }
    __syncthreads();
    const unsigned T = (unsigned)sT;
    const int C = (int)hist[T];
    __syncthreads();

    // ========== compact candidates from smem keys ==========
    const int NS = (C <= CANDP) ? CANDP : CANDF;
    #pragma unroll
    for (int c = 0; c < 4; c++) {
        uint4 kv = skeys4[c * 1024 + tid];
        int base = (c * 1024 + tid) * 4;
        if ((kv.x >> 20) <= T) {
            int pos = atomicAdd(&sCnt, 1);
            if (pos < CANDF) cand[pos] = ((unsigned long long)kv.x << 32) | (unsigned)(base + 0);
        }
        if ((kv.y >> 20) <= T) {
            int pos = atomicAdd(&sCnt, 1);
            if (pos < CANDF) cand[pos] = ((unsigned long long)kv.y << 32) | (unsigned)(base + 1);
        }
        if ((kv.z >> 20) <= T) {
            int pos = atomicAdd(&sCnt, 1);
            if (pos < CANDF) cand[pos] = ((unsigned long long)kv.z << 32) | (unsigned)(base + 2);
        }
        if ((kv.w >> 20) <= T) {
            int pos = atomicAdd(&sCnt, 1);
            if (pos < CANDF) cand[pos] = ((unsigned long long)kv.w << 32) | (unsigned)(base + 3);
        }
    }
    __syncthreads();
    for (int p = C + tid; p < NS; p += 1024)
        cand[p] = 0xffffffffffffffffull;
    __syncthreads();

    bitonic_hybrid(cand, NS, tid);
    // keys/hist dead from here; rowsbuf takes over [0, 161792)

    // ========== Stage B1: coalesced copy of top-512 rows to smem ==========
    for (int rr = wid; rr < PSEL; rr += 32) {
        unsigned long long key = cand[rr];          // uniform -> broadcast LDS
        int idx = (int)(key & 0xffffffffu);
        const float* r = reg + (size_t)(img * NN + idx) * REG_CH;
        float* dst = rowsbuf + rr * RSTRIDE;
        dst[lane]      = r[lane];
        dst[32 + lane] = r[32 + lane];
        if (lane < 12)       dst[64 + lane] = r[64 + lane];
        else if (lane < 15)  dst[64 + lane] = xyz[(size_t)(img * NN + idx) * 3 + (lane - 12)];
        if (lane == 15) scoreS[rr] = key_to_score((unsigned)(key >> 32));
    }
    __syncthreads();

    // ========== Stage B2: decode from smem (thread-per-row, conflict-free) ==========
    const float ah = anchor[0], aw = anchor[1], al = anchor[2];
    if (tid < PSEL) {
        const float* r = rowsbuf + tid * RSTRIDE;

        int xb = 0; float bv = r[0];
        #pragma unroll
        for (int t = 1; t < 12; t++) if (r[t] > bv) { bv = r[t]; xb = t; }
        int zb = 0; bv = r[12];
        #pragma unroll
        for (int t = 1; t < 12; t++) if (r[12 + t] > bv) { bv = r[12 + t]; zb = t; }

        float pos_x = __fadd_rn(__fsub_rn(__fadd_rn(__fmul_rn((float)xb, 0.5f), 0.25f), 3.0f),
                                __fmul_rn(r[24 + xb], 0.5f));
        float pos_z = __fadd_rn(__fsub_rn(__fadd_rn(__fmul_rn((float)zb, 0.5f), 0.25f), 3.0f),
                                __fmul_rn(r[36 + zb], 0.5f));
        float x = __fadd_rn(pos_x, r[76]);
        float z = __fadd_rn(pos_z, r[78]);
        float y = __fadd_rn(r[77], r[48]);

        int rb = 0; bv = r[49];
        #pragma unroll
        for (int t = 1; t < 12; t++) if (r[49 + t] > bv) { bv = r[49 + t]; rb = t; }
        float ry = __fadd_rn(__fmul_rn((float)rb, APC_F),
                             __fmul_rn(r[61 + rb], APC_HALF_F));
        float rem = fmodf(ry, TWO_PI_F);
        if (rem != 0.0f && rem < 0.0f) rem = __fadd_rn(rem, TWO_PI_F);
        ry = rem;
        if (ry > PI_F) ry = __fsub_rn(ry, TWO_PI_F);

        float h = __fadd_rn(__fmul_rn(r[73], ah), ah);
        float w = __fadd_rn(__fmul_rn(r[74], aw), aw);
        float l = __fadd_rn(__fmul_rn(r[75], al), al);
        y = __fadd_rn(y, __fmul_rn(h, 0.5f));

        float* bo = boxS + tid * 7;
        bo[0] = x; bo[1] = y; bo[2] = z; bo[3] = h; bo[4] = w; bo[5] = l; bo[6] = ry;

        float x1 = __fsub_rn(x, __fmul_rn(l, 0.5f));
        float x2 = __fadd_rn(x, __fmul_rn(l, 0.5f));
        float z1 = __fsub_rn(z, __fmul_rn(w, 0.5f));
        float z2 = __fadd_rn(z, __fmul_rn(w, 0.5f));
        sbev[tid] = make_float4(x1, z1, x2, z2);
        sar[tid] = __fmul_rn(__fsub_rn(x2, x1), __fsub_rn(z2, z1));
    }
    __syncthreads();   // rowsbuf dead; sup may now overwrite [0,32768)

    // ========== Stage C: balanced pairwise suppression bitmask + zrow ==========
    {
        const int ia = tid & 255;                // 0..255
        const int wset = (tid >> 8) & 3;         // 0..3
        #pragma unroll
        for (int half = 0; half < 2; half++) {
            const int i = half ? (PSEL - 1 - ia) : ia;
            float4 bi = sbev[i];
            float ai = sar[i];
            unsigned any = 0;
            #pragma unroll
            for (int p = 0; p < 4; p++) {
                int w = wset + 4 * p;
                unsigned bits = 0;
                int jbase = w << 5;
                if (jbase + 31 > i) {
                    #pragma unroll 4
                    for (int b = 0; b < 32; b++) {
                        int j = jbase + b;
                        if (j <= i) continue;
                        float4 bj = sbev[j];
                        float iw = fmaxf(__fsub_rn(fminf(bi.z, bj.z), fmaxf(bi.x, bj.x)), 0.0f);
                        float ih = fmaxf(__fsub_rn(fminf(bi.w, bj.w), fmaxf(bi.y, bj.y)), 0.0f);
                        float inter = __fmul_rn(iw, ih);
                        if (inter > 0.0f) {
                            float denom = __fsub_rn(__fadd_rn(ai, sar[j]), inter);
                            float iou = __fdiv_rn(inter, denom);
                            if (iou > NMS_THRESH) bits |= (1u << b);
                        }
                    }
                }
                sup[i * 16 + w] = bits;
                any |= bits;
            }
            if (any) atomicOr(&zrow[i >> 5], 1u << (i & 31));
        }
    }
    __syncthreads();

    // ========== Stage D: bulk-skip greedy (warp 0) ==========
    if (wid == 0) {
        unsigned A = (lane < 16) ? 0xffffffffu : 0u;   // alive bitmap
        unsigned Z = (lane < 16) ? zrow[lane] : 0u;    // suppressor flags
        int cnt = 0;
        int w = 0;
        while (cnt < POST && w < 16) {
            unsigned word = __shfl_sync(0xffffffffu, A, w);
            unsigned zw   = __shfl_sync(0xffffffffu, Z, w);
            unsigned danger = word & zw;
            if (danger == 0) {
                // no alive suppressor in this word: emit all alive bits at once
                int nb = __popc(word);
                int take = min(nb, POST - cnt);
                if (lane < take) {
                    int bit = __fns(word, 0, lane + 1);
                    keep[cnt + lane] = (w << 5) + bit;
                }
                cnt += take;
                w++;
            } else {
                int bs = __ffs(danger) - 1;            // first alive suppressor
                unsigned prefix = word & ((1u << bs) - 1u);   // bs==0 -> 0
                int nb = __popc(prefix);
                int take = min(nb, POST - cnt);
                if (lane < take) {
                    int bit = __fns(prefix, 0, lane + 1);
                    keep[cnt + lane] = (w << 5) + bit;
                }
                cnt += take;
                if (cnt >= POST) break;
                // keep the suppressor, apply its row
                int bi = (w << 5) + bs;
                if (lane == 0) keep[cnt] = bi;
                cnt++;
                unsigned srow = (lane < 16) ? sup[bi * 16 + lane] : 0u;
                A &= ~srow;
                if (lane == w) {
                    unsigned clr = (bs == 31) ? 0xffffffffu : ((1u << (bs + 1)) - 1u);
                    A &= ~clr;   // bits <= bs consumed
                }
                // stay on word w for remaining bits
            }
        }
        if (lane == 0) sKeepCnt = cnt;
    }
    __syncthreads();

    // ========== Stage E: gather output ==========
    const int cnt = sKeepCnt;
    float* ob = out + (size_t)img * POST * 7;
    float* os = out + (size_t)BB * POST * 7 + (size_t)img * POST;
    if (tid < POST) {
        int p = tid;
        if (p < cnt) {
            int ki = keep[p];
            const float* bo = boxS + ki * 7;
            #pragma unroll
            for (int c = 0; c < 7; c++) ob[p * 7 + c] = bo[c];
            os[p] = scoreS[ki];
        } else {
            #pragma unroll
            for (int c = 0; c < 7; c++) ob[p * 7 + c] = 0.0f;
            os[p] = 0.0f;
        }
    }
}

// ============================================================
extern "C" void kernel_launch(void* const* d_in, const int* in_sizes, int n_in,
                              void* d_out, int out_size) {
    const float* scores = (const float*)d_in[0];   // (B,N)
    const float* reg    = (const float*)d_in[1];   // (B,N,76)
    const float* xyz    = (const float*)d_in[2];   // (B,N,3)
    const float* anchor = (const float*)d_in[3];   // (3,)
    float* out = (float*)d_out;

    static bool attr_set = false;
    if (!attr_set) {
        cudaFuncSetAttribute(fused_kernel,
                             cudaFuncAttributeMaxDynamicSharedMemorySize,
                             SMEM_BYTES);
        attr_set = true;
    }

    fused_kernel<<<BB, 1024, SMEM_BYTES>>>(scores, reg, xyz, anchor, out);
}

// round 10
// speedup vs baseline: 2.5770x; 1.8058x over previous
#include <cuda_runtime.h>
#include <math.h>

// ---- problem config ----
#define BB 4
#define NN 16384
#define REG_CH 76
#define POST 128
#define PSEL 256               // candidate budget (128th kept ~rank 130; 2x margin)
#define MWS (PSEL / 32)        // sup words per row = 8
#define CANDP 512              // primary sort size
#define CANDM 1024             // mid fallback
#define CANDF 4096             // max fallback
#define NMS_THRESH 0.8f
#define TWO_PI_F 6.2831853071795864769f
#define PI_F 3.14159265358979323846f
#define APC_F 0.52359877559829887308f       // 2pi/12
#define APC_HALF_F 0.26179938779914943654f  // pi/12

#define RSTRIDE 79             // 76 reg + 3 xyz; odd -> conflict-free LDS

// ---- dynamic smem layout (bytes); regions time-multiplexed ----
// phase 1 (hist/compact/sort): keys [0,65536) | hist [65536,81920) | cand [81920,114688)
// phase 2 (copy/decode):       rowsbuf [0,80896) | cand | score/bev/sar/box high
// phase 3 (mask/greedy):       sup [0,8192) | bev/sar/box/score high
#define OFF_KEYS   0                        // 16384 u32 = 65536
#define OFF_ROWS   0                        // 256*79*4 = 80896
#define OFF_SUP    0                        // 256*8*4 = 8192 (phase 3)
#define OFF_HIST   65536                    // 4096 u32 = 16384
#define OFF_CAND   81920                    // 4096 u64 = 32768 -> 114688
#define OFF_SCORE  114688                   // 256 f32 = 1024
#define OFF_BEV4   115712                   // 256 float4 = 4096
#define OFF_SAR    119808                   // 256 f32 = 1024
#define OFF_BOX    120832                   // 256*7 f32 = 7168 -> 128000
#define SMEM_BYTES 128000

__device__ __forceinline__ unsigned desc_key(float f) {
    unsigned u = __float_as_uint(f);
    unsigned asc = (u & 0x80000000u) ? ~u : (u | 0x80000000u);
    return ~asc;   // ascending key order == descending score order
}
__device__ __forceinline__ float key_to_score(unsigned desc) {
    unsigned asc = ~desc;
    unsigned u = (asc & 0x80000000u) ? (asc ^ 0x80000000u) : ~asc;
    return __uint_as_float(u);
}

// hybrid bitonic sort, n power of 2 (512..4096), 1024 threads.
__device__ __forceinline__ void bitonic_hybrid(unsigned long long* a, int n, int tid) {
    const int lane = tid & 31;
    const int wid = tid >> 5;
    for (int k = 2; k <= n; k <<= 1) {
        for (int j = k >> 1; j >= 32; j >>= 1) {
            for (int i = tid; i < n; i += 1024) {
                int ixj = i ^ j;
                if (ixj > i) {
                    unsigned long long x = a[i], y = a[ixj];
                    bool asc = ((i & k) == 0);
                    if ((x > y) == asc) { a[i] = y; a[ixj] = x; }
                }
            }
            __syncthreads();
        }
        int jtop = (k >> 1) < 16 ? (k >> 1) : 16;
        for (int g = wid; g < (n >> 5); g += 32) {
            int i = (g << 5) + lane;
            unsigned long long v = a[i];
            bool asc = ((i & k) == 0);
            for (int j = jtop; j >= 1; j >>= 1) {
                unsigned long long p = __shfl_xor_sync(0xffffffffu, v, j);
                bool takemin = (((lane & j) == 0) == asc);
                v = takemin ? (v < p ? v : p) : (v > p ? v : p);
            }
            a[i] = v;
        }
        __syncthreads();
    }
}

// ============================================================
// One block per image.
// ============================================================
__global__ void __launch_bounds__(1024, 1)
fused_kernel(const float* __restrict__ scores,
             const float* __restrict__ reg,
             const float* __restrict__ xyz,
             const float* __restrict__ anchor,
             float* __restrict__ out) {
    extern __shared__ char sm[];
    uint4*    skeys4 = (uint4*)(sm + OFF_KEYS);
    unsigned* hist = (unsigned*)(sm + OFF_HIST);
    unsigned long long* cand = (unsigned long long*)(sm + OFF_CAND);
    float* rowsbuf = (float*)(sm + OFF_ROWS);
    unsigned* sup = (unsigned*)(sm + OFF_SUP);
    float4* sbev = (float4*)(sm + OFF_BEV4);     // (x1,z1,x2,z2)
    float* sar = (float*)(sm + OFF_SAR);
    float* boxS = (float*)(sm + OFF_BOX);
    float* scoreS = (float*)(sm + OFF_SCORE);

    __shared__ unsigned wsum[32];
    __shared__ unsigned zrow[MWS];    // per-box "suppresses anything" bitmap
    __shared__ int sT, sCnt, sKeepCnt;
    __shared__ int keep[POST];

    const int img = blockIdx.x;
    const int tid = threadIdx.x;
    const int lane = tid & 31;
    const int wid = tid >> 5;
    const float4* sc4 = (const float4*)(scores + (size_t)img * NN);

    // ========== Stage A: single-pass keys + histogram ==========
    for (int b = tid; b < 4096; b += 1024) hist[b] = 0;
    if (tid == 0) { sT = 4096; sCnt = 0; }
    if (tid < MWS) zrow[tid] = 0;
    __syncthreads();

    #pragma unroll
    for (int c = 0; c < 4; c++) {
        float4 v = sc4[c * 1024 + tid];
        unsigned k0 = desc_key(v.x), k1 = desc_key(v.y);
        unsigned k2 = desc_key(v.z), k3 = desc_key(v.w);
        skeys4[c * 1024 + tid] = make_uint4(k0, k1, k2, k3);
        atomicAdd(&hist[k0 >> 20], 1u);
        atomicAdd(&hist[k1 >> 20], 1u);
        atomicAdd(&hist[k2 >> 20], 1u);
        atomicAdd(&hist[k3 >> 20], 1u);
    }
    __syncthreads();

    // blocked inclusive prefix scan of hist[4096]
    {
        int b0 = tid * 4;
        unsigned v0 = hist[b0], v1 = hist[b0 + 1], v2 = hist[b0 + 2], v3 = hist[b0 + 3];
        unsigned i1 = v0 + v1, i2 = i1 + v2, i3 = i2 + v3;
        unsigned x = i3;
        #pragma unroll
        for (int d = 1; d < 32; d <<= 1) {
            unsigned y = __shfl_up_sync(0xffffffffu, x, d);
            if (lane >= d) x += y;
        }
        if (lane == 31) wsum[wid] = x;
        __syncthreads();
        if (wid == 0) {
            unsigned w = wsum[lane];
            #pragma unroll
            for (int d = 1; d < 32; d <<= 1) {
                unsigned y = __shfl_up_sync(0xffffffffu, w, d);
                if (lane >= d) w += y;
            }
            wsum[lane] = w;
        }
        __syncthreads();
        unsigned excl = ((wid > 0) ? wsum[wid - 1] : 0u) + (x - i3);
        hist[b0]     = excl + v0;
        hist[b0 + 1] = excl + i1;
        hist[b0 + 2] = excl + i2;
        hist[b0 + 3] = excl + i3;
        __syncthreads();
        #pragma unroll
        for (int k = 0; k < 4; k++)
            if (hist[b0 + k] >= PSEL) atomicMin(&sT, b0 + k);
    }
    __syncthreads();
    const unsigned T = (unsigned)sT;
    const int C = (int)hist[T];
    __syncthreads();

    // ========== compact candidates from smem keys ==========
    const int NS = (C <= CANDP) ? CANDP : ((C <= CANDM) ? CANDM : CANDF);
    #pragma unroll
    for (int c = 0; c < 4; c++) {
        uint4 kv = skeys4[c * 1024 + tid];
        int base = (c * 1024 + tid) * 4;
        if ((kv.x >> 20) <= T) {
            int pos = atomicAdd(&sCnt, 1);
            if (pos < CANDF) cand[pos] = ((unsigned long long)kv.x << 32) | (unsigned)(base + 0);
        }
        if ((kv.y >> 20) <= T) {
            int pos = atomicAdd(&sCnt, 1);
            if (pos < CANDF) cand[pos] = ((unsigned long long)kv.y << 32) | (unsigned)(base + 1);
        }
        if ((kv.z >> 20) <= T) {
            int pos = atomicAdd(&sCnt, 1);
            if (pos < CANDF) cand[pos] = ((unsigned long long)kv.z << 32) | (unsigned)(base + 2);
        }
        if ((kv.w >> 20) <= T) {
            int pos = atomicAdd(&sCnt, 1);
            if (pos < CANDF) cand[pos] = ((unsigned long long)kv.w << 32) | (unsigned)(base + 3);
        }
    }
    __syncthreads();
    for (int p = C + tid; p < NS; p += 1024)
        cand[p] = 0xffffffffffffffffull;
    __syncthreads();

    bitonic_hybrid(cand, NS, tid);
    // keys/hist dead from here; rowsbuf takes over [0, 80896)

    // ========== Stage B1: coalesced copy of top-256 rows to smem ==========
    for (int rr = wid; rr < PSEL; rr += 32) {
        unsigned long long key = cand[rr];          // uniform -> broadcast LDS
        int idx = (int)(key & 0xffffffffu);
        const float* r = reg + (size_t)(img * NN + idx) * REG_CH;
        float* dst = rowsbuf + rr * RSTRIDE;
        dst[lane]      = r[lane];
        dst[32 + lane] = r[32 + lane];
        if (lane < 12)       dst[64 + lane] = r[64 + lane];
        else if (lane < 15)  dst[64 + lane] = xyz[(size_t)(img * NN + idx) * 3 + (lane - 12)];
        if (lane == 15) scoreS[rr] = key_to_score((unsigned)(key >> 32));
    }
    __syncthreads();

    // ========== Stage B2: decode from smem (thread-per-row, conflict-free) ==========
    const float ah = anchor[0], aw = anchor[1], al = anchor[2];
    if (tid < PSEL) {
        const float* r = rowsbuf + tid * RSTRIDE;

        int xb = 0; float bv = r[0];
        #pragma unroll
        for (int t = 1; t < 12; t++) if (r[t] > bv) { bv = r[t]; xb = t; }
        int zb = 0; bv = r[12];
        #pragma unroll
        for (int t = 1; t < 12; t++) if (r[12 + t] > bv) { bv = r[12 + t]; zb = t; }

        float pos_x = __fadd_rn(__fsub_rn(__fadd_rn(__fmul_rn((float)xb, 0.5f), 0.25f), 3.0f),
                                __fmul_rn(r[24 + xb], 0.5f));
        float pos_z = __fadd_rn(__fsub_rn(__fadd_rn(__fmul_rn((float)zb, 0.5f), 0.25f), 3.0f),
                                __fmul_rn(r[36 + zb], 0.5f));
        float x = __fadd_rn(pos_x, r[76]);
        float z = __fadd_rn(pos_z, r[78]);
        float y = __fadd_rn(r[77], r[48]);

        int rb = 0; bv = r[49];
        #pragma unroll
        for (int t = 1; t < 12; t++) if (r[49 + t] > bv) { bv = r[49 + t]; rb = t; }
        float ry = __fadd_rn(__fmul_rn((float)rb, APC_F),
                             __fmul_rn(r[61 + rb], APC_HALF_F));
        float rem = fmodf(ry, TWO_PI_F);
        if (rem != 0.0f && rem < 0.0f) rem = __fadd_rn(rem, TWO_PI_F);
        ry = rem;
        if (ry > PI_F) ry = __fsub_rn(ry, TWO_PI_F);

        float h = __fadd_rn(__fmul_rn(r[73], ah), ah);
        float w = __fadd_rn(__fmul_rn(r[74], aw), aw);
        float l = __fadd_rn(__fmul_rn(r[75], al), al);
        y = __fadd_rn(y, __fmul_rn(h, 0.5f));

        float* bo = boxS + tid * 7;
        bo[0] = x; bo[1] = y; bo[2] = z; bo[3] = h; bo[4] = w; bo[5] = l; bo[6] = ry;

        float x1 = __fsub_rn(x, __fmul_rn(l, 0.5f));
        float x2 = __fadd_rn(x, __fmul_rn(l, 0.5f));
        float z1 = __fsub_rn(z, __fmul_rn(w, 0.5f));
        float z2 = __fadd_rn(z, __fmul_rn(w, 0.5f));
        sbev[tid] = make_float4(x1, z1, x2, z2);
        sar[tid] = __fmul_rn(__fsub_rn(x2, x1), __fsub_rn(z2, z1));
    }
    __syncthreads();   // rowsbuf dead; sup may now overwrite [0,8192)

    // ========== Stage C: balanced pairwise suppression bitmask + zrow ==========
    // 128 row-pairs x 8 words = 1024 units; thread does (p, w) and (255-p, w)
    {
        const int pr = tid & 127;                // pair id
        const int w = tid >> 7;                  // word 0..7
        #pragma unroll
        for (int half = 0; half < 2; half++) {
            const int i = half ? (PSEL - 1 - pr) : pr;
            float4 bi = sbev[i];
            float ai = sar[i];
            unsigned bits = 0;
            int jbase = w << 5;
            if (jbase + 31 > i) {
                #pragma unroll 4
                for (int b = 0; b < 32; b++) {
                    int j = jbase + b;
                    if (j <= i) continue;
                    float4 bj = sbev[j];
                    float iw = fmaxf(__fsub_rn(fminf(bi.z, bj.z), fmaxf(bi.x, bj.x)), 0.0f);
                    float ih = fmaxf(__fsub_rn(fminf(bi.w, bj.w), fmaxf(bi.y, bj.y)), 0.0f);
                    float inter = __fmul_rn(iw, ih);
                    if (inter > 0.0f) {
                        float denom = __fsub_rn(__fadd_rn(ai, sar[j]), inter);
                        float iou = __fdiv_rn(inter, denom);
                        if (iou > NMS_THRESH) bits |= (1u << b);
                    }
                }
            }
            sup[i * MWS + w] = bits;
            if (bits) atomicOr(&zrow[i >> 5], 1u << (i & 31));
        }
    }
    __syncthreads();

    // ========== Stage D: bulk-skip greedy (warp 0) ==========
    if (wid == 0) {
        unsigned A = (lane < MWS) ? 0xffffffffu : 0u;   // alive bitmap
        unsigned Z = (lane < MWS) ? zrow[lane] : 0u;    // suppressor flags
        int cnt = 0;
        int w = 0;
        while (cnt < POST && w < MWS) {
            unsigned word = __shfl_sync(0xffffffffu, A, w);
            unsigned zw   = __shfl_sync(0xffffffffu, Z, w);
            unsigned danger = word & zw;
            if (danger == 0) {
                int nb = __popc(word);
                int take = min(nb, POST - cnt);
                if (lane < take) {
                    int bit = __fns(word, 0, lane + 1);
                    keep[cnt + lane] = (w << 5) + bit;
                }
                cnt += take;
                w++;
            } else {
                int bs = __ffs(danger) - 1;            // first alive suppressor
                unsigned prefix = word & ((1u << bs) - 1u);
                int nb = __popc(prefix);
                int take = min(nb, POST - cnt);
                if (lane < take) {
                    int bit = __fns(prefix, 0, lane + 1);
                    keep[cnt + lane] = (w << 5) + bit;
                }
                cnt += take;
                if (cnt >= POST) break;
                int bi = (w << 5) + bs;
                if (lane == 0) keep[cnt] = bi;
                cnt++;
                unsigned srow = (lane < MWS) ? sup[bi * MWS + lane] : 0u;
                A &= ~srow;
                if (lane == w) {
                    unsigned clr = (bs == 31) ? 0xffffffffu : ((1u << (bs + 1)) - 1u);
                    A &= ~clr;   // bits <= bs consumed
                }
            }
        }
        if (lane == 0) sKeepCnt = cnt;
    }
    __syncthreads();

    // ========== Stage E: gather output ==========
    const int cnt = sKeepCnt;
    float* ob = out + (size_t)img * POST * 7;
    float* os = out + (size_t)BB * POST * 7 + (size_t)img * POST;
    if (tid < POST) {
        int p = tid;
        if (p < cnt) {
            int ki = keep[p];
            const float* bo = boxS + ki * 7;
            #pragma unroll
            for (int c = 0; c < 7; c++) ob[p * 7 + c] = bo[c];
            os[p] = scoreS[ki];
        } else {
            #pragma unroll
            for (int c = 0; c < 7; c++) ob[p * 7 + c] = 0.0f;
            os[p] = 0.0f;
        }
    }
}

// ============================================================
extern "C" void kernel_launch(void* const* d_in, const int* in_sizes, int n_in,
                              void* d_out, int out_size) {
    const float* scores = (const float*)d_in[0];   // (B,N)
    const float* reg    = (const float*)d_in[1];   // (B,N,76)
    const float* xyz    = (const float*)d_in[2];   // (B,N,3)
    const float* anchor = (const float*)d_in[3];   // (3,)
    float* out = (float*)d_out;

    static bool attr_set = false;
    if (!attr_set) {
        cudaFuncSetAttribute(fused_kernel,
                             cudaFuncAttributeMaxDynamicSharedMemorySize,
                             SMEM_BYTES);
        attr_set = true;
    }

    fused_kernel<<<BB, 1024, SMEM_BYTES>>>(scores, reg, xyz, anchor, out);
}